// round 12
// baseline (speedup 1.0000x reference)
#include <cuda_runtime.h>
#include <math.h>
#include <stdint.h>

#define NTASK 16
#define NEMB  25
#define DIM   512
#define HID   1024
#define NTRIP 2000
#define NCPT  64
#define NBLK  128              // one wave -> grid barrier safe

#define SX_STRIDE 516          // floats; 516%32=4 -> conflict-free A frags; /4=129
#define B_STRIDE  392          // floats; 392%32=8 -> conflict-free B frags
#define SX_BYTES  (32*SX_STRIDE*4)        // 66048
#define BSTAGE_BYTES (16*B_STRIDE*4)      // 25088
#define DSM_BYTES (SX_BYTES + 3*BSTAGE_BYTES)   // 141312

// ---------------- scratch ----------------
__device__ unsigned g_trip[NTASK*NTRIP];
__device__ int      g_cnt[NTASK];
__device__ float    g_q[NTASK*HID];
__device__ float    g_pooled[NTASK*DIM];
__device__ float    g_t1[NTASK*HID];
__device__ float    g_t2[NTASK*DIM];
__device__ unsigned g_bcnt[5];
__device__ unsigned g_bgen[5];

__device__ __forceinline__ float warp_sum(float v) {
    #pragma unroll
    for (int o = 16; o > 0; o >>= 1) v += __shfl_xor_sync(0xffffffffu, v, o);
    return v;
}
__device__ __forceinline__ uint32_t s2u(const void* p) {
    return (uint32_t)__cvta_generic_to_shared(p);
}
__device__ __forceinline__ void cpa16(uint32_t dst, const float* src) {
    asm volatile("cp.async.ca.shared.global [%0], [%1], 16;" :: "r"(dst), "l"(src));
}
#define MBAR1 asm volatile("bar.sync 1, 256;" ::: "memory")
#define CBAR2 asm volatile("bar.sync 2, 256;" ::: "memory")

__device__ __forceinline__ void grid_barrier(int s, unsigned nb) {
    __syncthreads();
    if (threadIdx.x == 0) {
        unsigned g0 = *((volatile unsigned*)&g_bgen[s]);
        __threadfence();
        unsigned old = atomicAdd(&g_bcnt[s], 1u);
        if (old == nb - 1u) {
            g_bcnt[s] = 0u;
            __threadfence();
            atomicAdd(&g_bgen[s], 1u);
        } else {
            while (*((volatile unsigned*)&g_bgen[s]) == g0) { }
            __threadfence();
        }
    }
    __syncthreads();
}

__device__ __forceinline__ void head_prefetch(const float* __restrict__ W,
                                              int Nout, int jb, int kb, int tid,
                                              float* wv) {
    int j  = jb*64 + (tid & 63);
    int kh = tid >> 6;
    #pragma unroll
    for (int ii = 0; ii < 8; ii++)
        wv[ii] = __ldg(&W[(size_t)(kb*64 + kh*8 + ii)*Nout + j]);
}

__device__ __forceinline__ void head_compute(const float* __restrict__ in,
                                             const float* __restrict__ bvec,
                                             const int* __restrict__ cntp,
                                             float* __restrict__ outp,
                                             int Nin, int Nout, int mode,
                                             int jb, int kb,
                                             float (*sf)[16], int tid,
                                             const float* wv) {
    int kb64 = kb * 64;
    for (int idx = tid; idx < 1024; idx += 512) {
        int il = idx >> 4, t = idx & 15;
        float v = in[t*Nin + kb64 + il];
        if (mode == 1)      v += (float)cntp[t] * bvec[kb64 + il];
        else if (mode == 2) v  = fmaxf(v + bvec[kb64 + il], 0.f);
        sf[il][t] = v;
    }
    __syncthreads();
    int j  = jb*64 + (tid & 63);
    int kh = tid >> 6;
    float acc[16];
    #pragma unroll
    for (int t = 0; t < 16; t++) acc[t] = 0.f;
    const float4* sf4 = reinterpret_cast<const float4*>(sf);
    #pragma unroll
    for (int ii = 0; ii < 8; ii++) {
        int i = (kh << 3) + ii;
        float w = wv[ii];
        float4 f0 = sf4[i*4 + 0];
        float4 f1 = sf4[i*4 + 1];
        float4 f2 = sf4[i*4 + 2];
        float4 f3 = sf4[i*4 + 3];
        acc[0]  += f0.x*w; acc[1]  += f0.y*w; acc[2]  += f0.z*w; acc[3]  += f0.w*w;
        acc[4]  += f1.x*w; acc[5]  += f1.y*w; acc[6]  += f1.z*w; acc[7]  += f1.w*w;
        acc[8]  += f2.x*w; acc[9]  += f2.y*w; acc[10] += f2.z*w; acc[11] += f2.w*w;
        acc[12] += f3.x*w; acc[13] += f3.y*w; acc[14] += f3.z*w; acc[15] += f3.w*w;
    }
    #pragma unroll
    for (int t = 0; t < 16; t++)
        atomicAdd(&outp[t*Nout + j], acc[t]);
}

// ============================================================================
// ONE persistent kernel. Block (k=bid>>3, cb=bid&7):
//   stage A: [warps 0-7] tf32 GEMM tile 25(+7)x384 into smem (K=512 cp.async)
//            [warps 8-15, cb==0 only] triplet mining (overlapped, named bars)
//   -> grid barrier -> pool from smem tile -> heads -> final
// ============================================================================
__global__ __launch_bounds__(512) void omega_kernel(const float* __restrict__ X,
                                                    const float* __restrict__ W1,
                                                    const float* __restrict__ b1,
                                                    const float* __restrict__ W2,
                                                    const float* __restrict__ b2,
                                                    const float* __restrict__ W3,
                                                    const float* __restrict__ b3,
                                                    const float* __restrict__ W4,
                                                    const float* __restrict__ b4v,
                                                    const float* __restrict__ Wc,
                                                    const float* __restrict__ bc,
                                                    unsigned* __restrict__ trip,
                                                    int* __restrict__ cnt,
                                                    float* __restrict__ q,
                                                    float* __restrict__ pooled,
                                                    float* __restrict__ t1,
                                                    float* __restrict__ t2,
                                                    float* __restrict__ out) {
    extern __shared__ char dsm[];
    float*       sX   = reinterpret_cast<float*>(dsm);
    const float4* sX4 = reinterpret_cast<const float4*>(dsm);
    float*       Bb   = reinterpret_cast<float*>(dsm + SX_BYTES);
    float*       sOut = Bb;                        // alias: valid after mainloop
    uint32_t sxu = s2u(sX);
    uint32_t bu  = s2u(Bb);

    __shared__ float D[NEMB][NEMB];
    __shared__ float invn[NEMB], sqv[NEMB];
    __shared__ int wcnt[8];
    __shared__ int base_sh;
    __shared__ unsigned strip[NTRIP];
    __shared__ float4 red[16][32];
    __shared__ float sf[64][16];
    __shared__ float fred[8][64];
    __shared__ float sc[NCPT];

    int bid = blockIdx.x;
    int tid = threadIdx.x;
    unsigned nb = gridDim.x;
    int k  = bid >> 3;
    int cb = bid & 7;
    int w = tid >> 5, lane = tid & 31;
    int grp = lane >> 2, tid4 = lane & 3;

    // ---- zero atomic accumulators ----
    {
        int gidx = bid*512 + tid;
        if (gidx < NTASK*DIM)  pooled[gidx] = 0.f;
        if (gidx < NTASK*HID)  t1[gidx]     = 0.f;
        if (gidx < NTASK*DIM)  t2[gidx]     = 0.f;
    }

    // ---- load X[k] (25x512) into sX (stride 516) via cp.async ----
    {
        const float* Xk = X + (size_t)k * NEMB * DIM;
        #pragma unroll
        for (int i = 0; i < 7; i++) {
            int c = tid + i*512;
            if (c < NEMB*128) {
                int row = c >> 7, cg = (c & 127) << 2;
                cpa16(sxu + (uint32_t)(row*SX_STRIDE + cg)*4u, Xk + row*DIM + cg);
            }
        }
        asm volatile("cp.async.commit_group;");
    }

    bool computer = (w < 8);
    float c[2][6][4];
    const float* bsrc[6];
    uint32_t bdst[6];

    if (computer) {
        #pragma unroll
        for (int mt = 0; mt < 2; mt++)
            #pragma unroll
            for (int nt = 0; nt < 6; nt++)
                #pragma unroll
                for (int r = 0; r < 4; r++) c[mt][nt][r] = 0.f;
        // B loader: 6 chunks of 16B per thread per stage (16 rows x 384 cols)
        #pragma unroll
        for (int i = 0; i < 6; i++) {
            int cc = tid + i*256;
            int row = cc / 96;
            int cg  = (cc - row*96) * 4;       // tile col 0..380
            int s   = cg >> 7;                 // W1 section
            int j   = cb*128 + (cg & 127);
            bsrc[i] = W1 + ((size_t)((s << 9) + row))*1024 + j;
            bdst[i] = (uint32_t)(row*B_STRIDE + cg) * 4u;
        }
        // prologue: stages 0,1
        #pragma unroll
        for (int st = 0; st < 2; st++) {
            int k0 = st * 16;
            #pragma unroll
            for (int i = 0; i < 6; i++)
                cpa16(bu + (uint32_t)st*BSTAGE_BYTES + bdst[i], bsrc[i] + (size_t)k0*1024);
            asm volatile("cp.async.commit_group;");
        }
        asm volatile("cp.async.wait_group 0;");   // sX + st0 + st1 complete
    } else {
        asm volatile("cp.async.wait_group 0;");   // own sX chunks
    }
    __syncthreads();                              // sX + prologue visible to all

    if (computer) {
        // ---------------- GEMM mainloop: 32 K-iters of BK=16 ----------------
        #pragma unroll 1
        for (int it = 0; it < 32; it++) {
            asm volatile("cp.async.wait_group 1;");
            CBAR2;
            if (it < 30) {
                int st = (it + 2) % 3;
                int k0 = (it + 2) * 16;
                #pragma unroll
                for (int i = 0; i < 6; i++)
                    cpa16(bu + (uint32_t)st*BSTAGE_BYTES + bdst[i], bsrc[i] + (size_t)k0*1024);
                asm volatile("cp.async.commit_group;");
            }
            const float* Bst = Bb + (it % 3) * (16*B_STRIDE);
            int kglo = it * 16;
            #pragma unroll
            for (int ks = 0; ks < 16; ks += 8) {
                uint32_t a[2][4], b[6][2];
                #pragma unroll
                for (int mt = 0; mt < 2; mt++) {
                    int mr = mt*16 + grp;
                    a[mt][0] = __float_as_uint(sX[mr*SX_STRIDE     + kglo + ks + tid4]);
                    a[mt][1] = __float_as_uint(sX[(mr+8)*SX_STRIDE + kglo + ks + tid4]);
                    a[mt][2] = __float_as_uint(sX[mr*SX_STRIDE     + kglo + ks + tid4 + 4]);
                    a[mt][3] = __float_as_uint(sX[(mr+8)*SX_STRIDE + kglo + ks + tid4 + 4]);
                }
                #pragma unroll
                for (int nt = 0; nt < 6; nt++) {
                    int nc = w*48 + nt*8 + grp;
                    b[nt][0] = __float_as_uint(Bst[(ks + tid4    )*B_STRIDE + nc]);
                    b[nt][1] = __float_as_uint(Bst[(ks + tid4 + 4)*B_STRIDE + nc]);
                }
                #pragma unroll
                for (int mt = 0; mt < 2; mt++)
                    #pragma unroll
                    for (int nt = 0; nt < 6; nt++) {
                        asm volatile(
                            "mma.sync.aligned.m16n8k8.row.col.f32.tf32.tf32.f32 "
                            "{%0,%1,%2,%3}, {%4,%5,%6,%7}, {%8,%9}, {%0,%1,%2,%3};"
                            : "+f"(c[mt][nt][0]), "+f"(c[mt][nt][1]),
                              "+f"(c[mt][nt][2]), "+f"(c[mt][nt][3])
                            : "r"(a[mt][0]), "r"(a[mt][1]), "r"(a[mt][2]), "r"(a[mt][3]),
                              "r"(b[nt][0]), "r"(b[nt][1]));
                    }
            }
        }
        CBAR2;   // all B reads done before overwriting region with sOut
        // store accumulators into sOut[row][col] (rows 25..31 garbage, unread)
        #pragma unroll
        for (int mt = 0; mt < 2; mt++) {
            int r0 = mt*16 + grp;
            int r1 = r0 + 8;
            #pragma unroll
            for (int nt = 0; nt < 6; nt++) {
                int col = w*48 + nt*8 + 2*tid4;
                sOut[r0*B_STRIDE + col]     = c[mt][nt][0];
                sOut[r0*B_STRIDE + col + 1] = c[mt][nt][1];
                sOut[r1*B_STRIDE + col]     = c[mt][nt][2];
                sOut[r1*B_STRIDE + col + 1] = c[mt][nt][3];
            }
        }
    } else if (cb == 0) {
        // ---------------- mining (task k), warps 8-15, overlapped ----------------
        int mtid = tid - 256;
        int mw = mtid >> 5;
        // raw norms -> invn, sqv
        for (int r = mw; r < NEMB; r += 8) {
            float s = 0.f;
            for (int d = lane; d < DIM; d += 32) { float v = sX[r*SX_STRIDE + d]; s += v*v; }
            s = warp_sum(s);
            if (lane == 0) { float iv = rsqrtf(s); invn[r] = iv; sqv[r] = s*iv*iv; }
        }
        MBAR1;
        // 300 pairwise distances (factored normalization)
        for (int p = mw; p < 300; p += 8) {
            int i = 0, rem = p;
            while (rem >= 24 - i) { rem -= 24 - i; i++; }
            int j = i + 1 + rem;
            float s = 0.f;
            for (int cc = lane; cc < 128; cc += 32) {
                float4 av = sX4[i*129 + cc];
                float4 bv = sX4[j*129 + cc];
                s += av.x*bv.x + av.y*bv.y + av.z*bv.z + av.w*bv.w;
            }
            s = warp_sum(s);
            if (lane == 0) {
                float d2 = sqv[i] + sqv[j] - 2.f*s*invn[i]*invn[j];
                float dd = sqrtf(fmaxf(d2, 0.f));
                D[i][j] = dd; D[j][i] = dd;
            }
        }
        MBAR1;
        if (mtid == 0) base_sh = 0;
        MBAR1;
        for (int rnd = 0; rnd < 8; rnd++) {
            int t = rnd*256 + mtid;
            bool f = false; unsigned pack = 0;
            if (t < NTRIP) {
                int a  = t / 80;
                int rm = t - a*80;
                int pi = rm / 20, ni = rm - (rm/20)*20;
                int lbl = a % 5, ga = a / 5;
                int pg = pi + (pi >= ga ? 1 : 0);
                int p  = lbl + 5*pg;
                int m  = ni >> 2, w2 = ni & 3;
                int wn2 = w2 + (w2 >= lbl ? 1 : 0);
                int n  = 5*m + wn2;
                float tm = D[a][n] - D[a][p];
                f = (tm > 0.f && tm <= 0.8f);
                pack = (unsigned)(a | (p << 5) | (n << 10));
            }
            unsigned bal = __ballot_sync(0xffffffffu, f);
            if (lane == 0) wcnt[mw] = __popc(bal);
            MBAR1;
            int off = base_sh;
            #pragma unroll
            for (int w8 = 0; w8 < 8; w8++) if (w8 < mw) off += wcnt[w8];
            off += __popc(bal & ((1u << lane) - 1u));
            if (f) trip[k*NTRIP + off] = pack;
            MBAR1;
            if (mtid == 0) {
                int s = 0;
                #pragma unroll
                for (int w8 = 0; w8 < 8; w8++) s += wcnt[w8];
                base_sh += s;
            }
            MBAR1;
        }
        if (mtid == 0) cnt[k] = base_sh;
    }
    __syncthreads();          // join compute/mining/idle
    grid_barrier(0, nb);      // trip/cnt visible to all blocks

    // ============================ pool (from sOut) ============================
    float w2v[8];
    head_prefetch(W2, DIM, cb, k, tid, w2v);
    {
        int n = cnt[k];
        const unsigned* tp = trip + k*NTRIP;
        for (int i = tid; i < n; i += 512) strip[i] = __ldg(&tp[i]);
        __syncthreads();
        int l4 = lane << 2;
        float4 b1v = *reinterpret_cast<const float4*>(&b1[(cb << 7) + l4]);
        int lo = (w * n) >> 4;
        int hi = ((w + 1) * n) >> 4;
        float4 acc0 = make_float4(0.f, 0.f, 0.f, 0.f);
        float4 acc1 = acc0;
        int cur_a = -1, cur_p = -1;
        float4 fa = acc0, fap = acc0;
        int t = lo;
        for (; t + 1 < hi; t += 2) {
            unsigned u0 = strip[t], u1 = strip[t+1];
            int a0 = u0 & 31, p0 = (u0 >> 5) & 31, n0 = (u0 >> 10) & 31;
            int a1 = u1 & 31, p1 = (u1 >> 5) & 31, n1 = (u1 >> 10) & 31;
            if (a0 != cur_a) {
                float4 g = *reinterpret_cast<const float4*>(&sOut[a0*B_STRIDE + l4]);
                fa.x = g.x + b1v.x; fa.y = g.y + b1v.y;
                fa.z = g.z + b1v.z; fa.w = g.w + b1v.w;
                cur_a = a0; cur_p = -1;
            }
            if (p0 != cur_p) {
                float4 g = *reinterpret_cast<const float4*>(&sOut[p0*B_STRIDE + 128 + l4]);
                fap.x = fa.x + g.x; fap.y = fa.y + g.y;
                fap.z = fa.z + g.z; fap.w = fa.w + g.w;
                cur_p = p0;
            }
            float4 gn0 = *reinterpret_cast<const float4*>(&sOut[n0*B_STRIDE + 256 + l4]);
            float4 fap0 = fap;
            if (a1 != cur_a) {
                float4 g = *reinterpret_cast<const float4*>(&sOut[a1*B_STRIDE + l4]);
                fa.x = g.x + b1v.x; fa.y = g.y + b1v.y;
                fa.z = g.z + b1v.z; fa.w = g.w + b1v.w;
                cur_a = a1; cur_p = -1;
            }
            if (p1 != cur_p) {
                float4 g = *reinterpret_cast<const float4*>(&sOut[p1*B_STRIDE + 128 + l4]);
                fap.x = fa.x + g.x; fap.y = fa.y + g.y;
                fap.z = fa.z + g.z; fap.w = fa.w + g.w;
                cur_p = p1;
            }
            float4 gn1 = *reinterpret_cast<const float4*>(&sOut[n1*B_STRIDE + 256 + l4]);
            acc0.x += fmaxf(fap0.x + gn0.x, 0.f);
            acc0.y += fmaxf(fap0.y + gn0.y, 0.f);
            acc0.z += fmaxf(fap0.z + gn0.z, 0.f);
            acc0.w += fmaxf(fap0.w + gn0.w, 0.f);
            acc1.x += fmaxf(fap.x + gn1.x, 0.f);
            acc1.y += fmaxf(fap.y + gn1.y, 0.f);
            acc1.z += fmaxf(fap.z + gn1.z, 0.f);
            acc1.w += fmaxf(fap.w + gn1.w, 0.f);
        }
        if (t < hi) {
            unsigned u = strip[t];
            int a = u & 31, p = (u >> 5) & 31, nn = (u >> 10) & 31;
            if (a != cur_a) {
                float4 g = *reinterpret_cast<const float4*>(&sOut[a*B_STRIDE + l4]);
                fa.x = g.x + b1v.x; fa.y = g.y + b1v.y;
                fa.z = g.z + b1v.z; fa.w = g.w + b1v.w;
                cur_a = a; cur_p = -1;
            }
            if (p != cur_p) {
                float4 g = *reinterpret_cast<const float4*>(&sOut[p*B_STRIDE + 128 + l4]);
                fap.x = fa.x + g.x; fap.y = fa.y + g.y;
                fap.z = fa.z + g.z; fap.w = fa.w + g.w;
                cur_p = p;
            }
            float4 gn = *reinterpret_cast<const float4*>(&sOut[nn*B_STRIDE + 256 + l4]);
            acc0.x += fmaxf(fap.x + gn.x, 0.f);
            acc0.y += fmaxf(fap.y + gn.y, 0.f);
            acc0.z += fmaxf(fap.z + gn.z, 0.f);
            acc0.w += fmaxf(fap.w + gn.w, 0.f);
        }
        acc0.x += acc1.x; acc0.y += acc1.y; acc0.z += acc1.z; acc0.w += acc1.w;
        red[w][lane] = acc0;
        __syncthreads();
        if (tid < 32) {
            float4 s = red[0][tid];
            #pragma unroll
            for (int g = 1; g < 16; g++) {
                float4 r = red[g][tid];
                s.x += r.x; s.y += r.y; s.z += r.z; s.w += r.w;
            }
            *reinterpret_cast<float4*>(&q[k*HID + (cb << 7) + (tid << 2)]) = s;
        }
    }
    grid_barrier(1, nb);

    head_compute(q, nullptr, nullptr, pooled, HID, DIM, 0, bid & 7, bid >> 3, sf, tid, w2v);
    float w3v[8];
    head_prefetch(W3, HID, bid & 15, bid >> 4, tid, w3v);
    grid_barrier(2, nb);

    head_compute(pooled, b2, cnt, t1, DIM, HID, 1, bid & 15, bid >> 4, sf, tid, w3v);
    float w4v[8];
    head_prefetch(W4, DIM, bid & 7, bid >> 3, tid, w4v);
    grid_barrier(3, nb);

    head_compute(t1, b3, nullptr, t2, HID, DIM, 2, bid & 7, bid >> 3, sf, tid, w4v);
    grid_barrier(4, nb);

    if (bid < NTASK) {
        int kk = bid;
        int cc = tid & 63, seg = tid >> 6;
        float acc = 0.f;
        const float* tk = t2 + kk*DIM;
        for (int i = seg*64; i < seg*64 + 64; i++)
            acc += (tk[i] + b4v[i]) * Wc[i*NCPT + cc];
        fred[seg][cc] = acc;
        __syncthreads();
        if (tid < NCPT) {
            float s = bc[cc];
            #pragma unroll
            for (int g = 0; g < 8; g++) s += fred[g][cc];
            sc[cc] = s;
        }
        __syncthreads();
        if (tid < NCPT) {
            float v = sc[cc];
            float mx = -1e30f;
            #pragma unroll
            for (int i = 0; i < NCPT; i++) mx = fmaxf(mx, sc[i]);
            float sum = 0.f;
            #pragma unroll
            for (int i = 0; i < NCPT; i++) sum += expf(sc[i] - mx);
            out[kk*NCPT + cc] = expf(v - mx) / sum;
        }
    }
}

// ---------------- launch ----------------
extern "C" void kernel_launch(void* const* d_in, const int* in_sizes, int n_in,
                              void* d_out, int out_size) {
    const float* X  = (const float*)d_in[0];
    const float* W1 = (const float*)d_in[1];
    const float* b1 = (const float*)d_in[2];
    const float* W2 = (const float*)d_in[3];
    const float* b2 = (const float*)d_in[4];
    const float* W3 = (const float*)d_in[5];
    const float* b3 = (const float*)d_in[6];
    const float* W4 = (const float*)d_in[7];
    const float* b4 = (const float*)d_in[8];
    const float* Wc = (const float*)d_in[9];
    const float* bc = (const float*)d_in[10];
    float* out = (float*)d_out;

    float *q, *pooled, *t1, *t2; unsigned* trip; int* cnt;
    cudaGetSymbolAddress((void**)&trip,   g_trip);
    cudaGetSymbolAddress((void**)&cnt,    g_cnt);
    cudaGetSymbolAddress((void**)&q,      g_q);
    cudaGetSymbolAddress((void**)&pooled, g_pooled);
    cudaGetSymbolAddress((void**)&t1,     g_t1);
    cudaGetSymbolAddress((void**)&t2,     g_t2);

    static int configured = 0;
    if (!configured) {
        cudaFuncSetAttribute(omega_kernel, cudaFuncAttributeMaxDynamicSharedMemorySize, DSM_BYTES);
        configured = 1;
    }

    omega_kernel<<<NBLK, 512, DSM_BYTES>>>(X, W1, b1, W2, b2, W3, b3, W4, b4, Wc, bc,
                                           trip, cnt, q, pooled, t1, t2, out);
}